// round 2
// baseline (speedup 1.0000x reference)
#include <cuda_runtime.h>
#include <math.h>

#define BT    4096
#define HID   256
#define TSTEP 64
#define BB    64

// ---------------- scratch (static device memory; no allocations) ----------------
__device__ float g_feat  [BT * HID];          // conv features (B*T, 256)
__device__ float g_gatesx[BT * 1024];         // x @ Wk + b
__device__ float g_lstm  [BT * HID];          // lstm hidden states
__device__ float g_pimlog[16777216];          // pim logits (4096 x 4096)
__device__ float g_pir   [BT * 36];           // pir probabilities
__device__ float g_entpir[BT];
__device__ float g_entpim[BT];
__device__ float g_ppim  [BT];                // pim prob of taken action
__device__ float g_vpred [BT];
__device__ float g_pgvals[BT];
__device__ float g_vfvals[BT];
__device__ float g_stats [2];                 // gae mean, std

__device__ __forceinline__ float leaky(float v) { return v > 0.f ? v : 0.2f * v; }
__device__ __forceinline__ float sigmoidf(float v) { return 1.f / (1.f + expf(-v)); }

// ---------------- fused conv stack: one block per image ----------------
__global__ __launch_bounds__(128) void conv_kernel(
    const float* __restrict__ x,
    const float* __restrict__ W1, const float* __restrict__ b1,
    const float* __restrict__ W2, const float* __restrict__ b2,
    const float* __restrict__ W3, const float* __restrict__ b3,
    const float* __restrict__ W4, const float* __restrict__ b4)
{
    __shared__ float sx[832];   // 13*8*8
    __shared__ float h1[384];   // 6*4*16
    __shared__ float h2[480];   // 5*3*32
    __shared__ float h3[128];   // 2*1*64
    const int img = blockIdx.x;
    const float* xin = x + img * 832;
    for (int i = threadIdx.x; i < 832; i += blockDim.x) sx[i] = xin[i];
    __syncthreads();

    // conv1: (13,8,8) -> (6,4,16), k=2 s=2
    for (int idx = threadIdx.x; idx < 384; idx += blockDim.x) {
        int oc = idx & 15, sp = idx >> 4;
        int ow = sp & 3, oh = sp >> 2;
        float v = b1[oc];
        #pragma unroll
        for (int kh = 0; kh < 2; kh++)
        #pragma unroll
        for (int kw = 0; kw < 2; kw++) {
            const float* xp = &sx[((oh * 2 + kh) * 8 + (ow * 2 + kw)) * 8];
            const float* wp = &W1[((kh * 2 + kw) * 8) * 16 + oc];
            #pragma unroll
            for (int ic = 0; ic < 8; ic++) v += xp[ic] * wp[ic * 16];
        }
        h1[idx] = leaky(v);
    }
    __syncthreads();

    // conv2: (6,4,16) -> (5,3,32), k=2 s=1
    for (int idx = threadIdx.x; idx < 480; idx += blockDim.x) {
        int oc = idx & 31, sp = idx >> 5;
        int ow = sp % 3, oh = sp / 3;
        float v = b2[oc];
        #pragma unroll
        for (int kh = 0; kh < 2; kh++)
        #pragma unroll
        for (int kw = 0; kw < 2; kw++) {
            const float* hp = &h1[((oh + kh) * 4 + (ow + kw)) * 16];
            const float* wp = &W2[((kh * 2 + kw) * 16) * 32 + oc];
            #pragma unroll
            for (int ic = 0; ic < 16; ic++) v += hp[ic] * wp[ic * 32];
        }
        h2[idx] = leaky(v);
    }
    __syncthreads();

    // conv3: (5,3,32) -> (2,1,64), k=2 s=2
    for (int idx = threadIdx.x; idx < 128; idx += blockDim.x) {
        int oc = idx & 63, oh = idx >> 6;
        float v = b3[oc];
        #pragma unroll
        for (int kh = 0; kh < 2; kh++)
        #pragma unroll
        for (int kw = 0; kw < 2; kw++) {
            const float* hp = &h2[((oh * 2 + kh) * 3 + kw) * 32];
            const float* wp = &W3[((kh * 2 + kw) * 32) * 64 + oc];
            #pragma unroll
            for (int ic = 0; ic < 32; ic++) v += hp[ic] * wp[ic * 64];
        }
        h3[idx] = leaky(v);
    }
    __syncthreads();

    // conv4 1x1: (2,1,64)->(2,1,128) + channels_first flatten: feat[2*oc+oh]
    for (int idx = threadIdx.x; idx < 256; idx += blockDim.x) {
        int oc = idx >> 1, oh = idx & 1;
        float v = b4[oc];
        #pragma unroll
        for (int ic = 0; ic < 64; ic++) v += h3[oh * 64 + ic] * W4[ic * 128 + oc];
        g_feat[img * 256 + idx] = leaky(v);
    }
}

// ---------------- tiled SGEMM with bias: C(M,N) = A(M,K) @ B(K,N) + bias ----------------
__global__ __launch_bounds__(256) void sgemm_bias_kernel(
    const float* __restrict__ A, const float* __restrict__ B,
    const float* __restrict__ bias, float* __restrict__ C,
    int M, int N, int K)
{
    const int BM = 128, BN = 128, BK = 8, TM = 8, TN = 8;
    __shared__ float As[BK][BM];
    __shared__ float Bs[BK][BN];
    const int bcol = blockIdx.x, brow = blockIdx.y;
    const int tid = threadIdx.x;
    const int tx = tid % (BN / TN);     // 0..15
    const int ty = tid / (BN / TN);     // 0..15
    float acc[TM][TN];
    #pragma unroll
    for (int m = 0; m < TM; m++)
        #pragma unroll
        for (int n = 0; n < TN; n++) acc[m][n] = 0.f;
    float ar[TM], br[TN];
    const float* Ab = A + (size_t)brow * BM * K;
    const float* Bb = B + (size_t)bcol * BN;

    for (int k0 = 0; k0 < K; k0 += BK) {
        #pragma unroll
        for (int i = tid; i < BM * BK; i += 256) {
            int r = i >> 3, c = i & 7;
            As[c][r] = Ab[r * K + k0 + c];
        }
        #pragma unroll
        for (int i = tid; i < BK * BN; i += 256) {
            int r = i >> 7, c = i & 127;
            Bs[r][c] = Bb[(size_t)(k0 + r) * N + c];
        }
        __syncthreads();
        #pragma unroll
        for (int kk = 0; kk < BK; kk++) {
            #pragma unroll
            for (int m = 0; m < TM; m++) ar[m] = As[kk][ty * TM + m];
            #pragma unroll
            for (int n = 0; n < TN; n++) br[n] = Bs[kk][tx * TN + n];
            #pragma unroll
            for (int m = 0; m < TM; m++)
                #pragma unroll
                for (int n = 0; n < TN; n++) acc[m][n] += ar[m] * br[n];
        }
        __syncthreads();
    }
    #pragma unroll
    for (int m = 0; m < TM; m++) {
        size_t row = (size_t)brow * BM + ty * TM + m;
        #pragma unroll
        for (int n = 0; n < TN; n++) {
            int col = bcol * BN + tx * TN + n;
            C[row * N + col] = acc[m][n] + bias[col];
        }
    }
}

// ---------------- LSTM: one block per 2 batch rows, sequential over T ----------------
__global__ __launch_bounds__(256) void lstm_kernel(const float* __restrict__ Wr)
{
    __shared__ float h[2][256];
    const int j = threadIdx.x;
    const int b0 = blockIdx.x * 2;
    h[0][j] = 0.f; h[1][j] = 0.f;
    float c0 = 0.f, c1 = 0.f;
    __syncthreads();

    for (int t = 0; t < TSTEP; t++) {
        const size_t row0 = ((size_t)b0 * TSTEP + t) * 1024;
        const size_t row1 = ((size_t)(b0 + 1) * TSTEP + t) * 1024;
        float acc[4][2];
        #pragma unroll
        for (int g = 0; g < 4; g++) {
            acc[g][0] = g_gatesx[row0 + g * 256 + j];
            acc[g][1] = g_gatesx[row1 + g * 256 + j];
        }
        #pragma unroll 4
        for (int k = 0; k < 256; k++) {
            float h0 = h[0][k], h1 = h[1][k];
            const float* w = &Wr[k * 1024 + j];
            #pragma unroll
            for (int g = 0; g < 4; g++) {
                float wv = __ldg(&w[g * 256]);
                acc[g][0] += wv * h0;
                acc[g][1] += wv * h1;
            }
        }
        float i0 = sigmoidf(acc[0][0]), f0 = sigmoidf(acc[1][0]);
        float g0 = tanhf(acc[2][0]),    o0 = sigmoidf(acc[3][0]);
        c0 = f0 * c0 + i0 * g0;
        float hn0 = o0 * tanhf(c0);
        float i1 = sigmoidf(acc[0][1]), f1 = sigmoidf(acc[1][1]);
        float g1 = tanhf(acc[2][1]),    o1 = sigmoidf(acc[3][1]);
        c1 = f1 * c1 + i1 * g1;
        float hn1 = o1 * tanhf(c1);
        __syncthreads();
        h[0][j] = hn0; h[1][j] = hn1;
        g_lstm[((size_t)b0 * TSTEP + t) * 256 + j] = hn0;
        g_lstm[((size_t)(b0 + 1) * TSTEP + t) * 256 + j] = hn1;
        __syncthreads();
    }
}

// ---------------- pir head: logits + softmax + entropy (one block per row) ----------------
__global__ __launch_bounds__(64) void pir_kernel(const float* __restrict__ pir_W,
                                                 const float* __restrict__ pir_b)
{
    __shared__ float sh[256];
    __shared__ float lg[36];
    const int row = blockIdx.x;
    const int tid = threadIdx.x;
    for (int i = tid; i < 256; i += blockDim.x) sh[i] = g_lstm[(size_t)row * 256 + i];
    __syncthreads();
    if (tid < 36) {
        float v = pir_b[tid];
        for (int k = 0; k < 256; k++) v += sh[k] * pir_W[k * 36 + tid];
        lg[tid] = v;
    }
    __syncthreads();
    if (tid == 0) {
        float mx = -1e30f;
        for (int c = 0; c < 36; c++) mx = fmaxf(mx, lg[c]);
        float s = 0.f;
        for (int c = 0; c < 36; c++) s += expf(lg[c] - mx);
        float ent = 0.f;
        for (int c = 0; c < 36; c++) {
            float p = expf(lg[c] - mx) / s;
            g_pir[row * 36 + c] = p;
            ent += p * logf(p);
        }
        g_entpir[row] = ent;   // sum p log p (negative)
    }
}

// ---------------- pim softmax + mask + renorm + entropy + gather ----------------
__global__ __launch_bounds__(256) void pim_softmax_kernel(const int* __restrict__ mask,
                                                          const int* __restrict__ a_taken)
{
    __shared__ float red[256];
    __shared__ float s_mx, s_S, s_SM;
    const int row = blockIdx.x;
    const int tid = threadIdx.x;
    const float* lg = g_pimlog + (size_t)row * 4096;
    const int* mrow = mask + (size_t)row * 4096;

    // max
    float mx = -1e30f;
    for (int j = tid; j < 4096; j += 256) mx = fmaxf(mx, lg[j]);
    red[tid] = mx; __syncthreads();
    for (int s = 128; s > 0; s >>= 1) { if (tid < s) red[tid] = fmaxf(red[tid], red[tid + s]); __syncthreads(); }
    if (tid == 0) s_mx = red[0];
    __syncthreads();
    mx = s_mx;

    // total sum-exp and masked sum-exp
    float ssum = 0.f, smsum = 0.f;
    for (int j = tid; j < 4096; j += 256) {
        float q = expf(lg[j] - mx);
        ssum += q;
        if (mrow[j]) smsum += q;
    }
    __syncthreads();
    red[tid] = ssum; __syncthreads();
    for (int s = 128; s > 0; s >>= 1) { if (tid < s) red[tid] += red[tid + s]; __syncthreads(); }
    if (tid == 0) s_S = red[0];
    __syncthreads();
    red[tid] = smsum; __syncthreads();
    for (int s = 128; s > 0; s >>= 1) { if (tid < s) red[tid] += red[tid + s]; __syncthreads(); }
    if (tid == 0) s_SM = red[0];
    __syncthreads();

    const float denom = (s_SM > 0.f) ? s_SM : s_S;

    // entropy over masked entries (mask==0 entries contribute exactly 0)
    float ent = 0.f;
    for (int j = tid; j < 4096; j += 256) {
        if (mrow[j]) {
            float p = expf(lg[j] - mx) / denom;
            if (p > 0.f) ent += p * logf(p);
        }
    }
    __syncthreads();
    red[tid] = ent; __syncthreads();
    for (int s = 128; s > 0; s >>= 1) { if (tid < s) red[tid] += red[tid + s]; __syncthreads(); }
    if (tid == 0) {
        g_entpim[row] = red[0];
        int a = a_taken[row];
        float q = expf(lg[a] - mx);
        g_ppim[row] = mrow[a] ? q / denom : 0.f;
    }
}

// ---------------- value head ----------------
__global__ __launch_bounds__(32) void vpred_kernel(const float* __restrict__ v_W,
                                                   const float* __restrict__ v_b)
{
    const int row = blockIdx.x;
    const int lane = threadIdx.x;
    float s = 0.f;
    for (int k = lane; k < 256; k += 32) s += g_lstm[(size_t)row * 256 + k] * v_W[k];
    for (int o = 16; o > 0; o >>= 1) s += __shfl_down_sync(0xffffffffu, s, o);
    if (lane == 0) g_vpred[row] = s + v_b[0];
}

// ---------------- block-wide double sum (blockDim must be 1024) ----------------
__device__ double block_sum_d(double v)
{
    __shared__ double rd[1024];
    const int tid = threadIdx.x;
    __syncthreads();
    rd[tid] = v; __syncthreads();
    for (int s = 512; s > 0; s >>= 1) { if (tid < s) rd[tid] += rd[tid + s]; __syncthreads(); }
    double r = rd[0];
    __syncthreads();
    return r;
}

__global__ __launch_bounds__(1024) void gae_stats_kernel(const float* __restrict__ GAE)
{
    const int tid = threadIdx.x;
    double s = 0.0;
    for (int i = tid; i < BT; i += 1024) s += (double)GAE[i];
    double tot = block_sum_d(s);
    double mean = tot / (double)BT;
    double v = 0.0;
    for (int i = tid; i < BT; i += 1024) { double d = (double)GAE[i] - mean; v += d * d; }
    double var = block_sum_d(v) / (double)BT;
    if (tid == 0) { g_stats[0] = (float)mean; g_stats[1] = (float)sqrt(var); }
}

__global__ void pg_terms_kernel(const float* __restrict__ lg_old,
                                const int* __restrict__ a_taken,
                                const float* __restrict__ GAE)
{
    const int i = blockIdx.x * blockDim.x + threadIdx.x;
    if (i >= BT) return;
    const float mean = g_stats[0], std = g_stats[1];
    float g = (GAE[i] - mean) / (std + 1e-8f);
    int a = a_taken[i];
    float p = ((i & 1) == 0) ? g_pir[i * 36 + a] : g_ppim[i];
    float lgn = logf(p);
    float rt = expf(lgn - lg_old[i]);
    float rtc = fminf(fmaxf(rt, 0.8f), 1.2f);
    g_pgvals[i] = fmaxf(-g * rt, -g * rtc);
}

// vf broadcast loss: block i sums over j
__global__ __launch_bounds__(256) void vf_kernel(const float* __restrict__ old_v,
                                                 const float* __restrict__ ret)
{
    __shared__ float red[256];
    const int i = blockIdx.x;
    const int tid = threadIdx.x;
    const float vp = g_vpred[i];
    float s = 0.f;
    for (int j = tid; j < BT; j += 256) {
        float r = ret[j];
        float ov = old_v[j];
        float d1 = vp - r;
        float dc = fminf(fmaxf(vp - ov, -0.2f), 0.2f);
        float d2 = ov + dc - r;
        s += fmaxf(d1 * d1, d2 * d2);
    }
    red[tid] = s; __syncthreads();
    for (int st = 128; st > 0; st >>= 1) { if (tid < st) red[tid] += red[tid + st]; __syncthreads(); }
    if (tid == 0) g_vfvals[i] = red[0];
}

__global__ __launch_bounds__(1024) void finalize_kernel(float* __restrict__ out)
{
    const int tid = threadIdx.x;
    double s = 0.0;
    for (int i = tid; i < BT; i += 1024) s += (double)g_pgvals[i];
    double pg = block_sum_d(s) / (double)BT;

    s = 0.0;
    for (int i = tid; i < BT; i += 1024) s += (double)g_entpir[i] + (double)g_entpim[i];
    double entropy = -block_sum_d(s);

    s = 0.0;
    for (int i = tid; i < BT; i += 1024) s += (double)g_vfvals[i];
    double vf = 0.5 * block_sum_d(s) / ((double)BT * (double)BT);

    if (tid == 0) {
        out[0] = (float)(pg - entropy + vf);
        out[1] = (float)pg;
        out[2] = (float)entropy;
        out[3] = (float)vf;
    }
}

// ---------------- launcher ----------------
extern "C" void kernel_launch(void* const* d_in, const int* in_sizes, int n_in,
                              void* d_out, int out_size)
{
    const float* x       = (const float*)d_in[0];
    const int*   mask    = (const int*)  d_in[1];
    const float* lg_old  = (const float*)d_in[2];
    const int*   a_taken = (const int*)  d_in[3];
    const float* GAE     = (const float*)d_in[4];
    const float* old_v   = (const float*)d_in[5];
    const float* rets    = (const float*)d_in[6];
    const float* W1 = (const float*)d_in[7];  const float* b1 = (const float*)d_in[8];
    const float* W2 = (const float*)d_in[9];  const float* b2 = (const float*)d_in[10];
    const float* W3 = (const float*)d_in[11]; const float* b3 = (const float*)d_in[12];
    const float* W4 = (const float*)d_in[13]; const float* b4 = (const float*)d_in[14];
    const float* lstm_k = (const float*)d_in[15];
    const float* lstm_r = (const float*)d_in[16];
    const float* lstm_b = (const float*)d_in[17];
    const float* pir_W  = (const float*)d_in[18];
    const float* pir_b  = (const float*)d_in[19];
    const float* pim_W  = (const float*)d_in[20];
    const float* pim_b  = (const float*)d_in[21];
    const float* v_W    = (const float*)d_in[22];
    const float* v_b    = (const float*)d_in[23];
    float* out = (float*)d_out;

    void *p_feat, *p_gatesx, *p_lstm, *p_pimlog;
    cudaGetSymbolAddress(&p_feat,   g_feat);
    cudaGetSymbolAddress(&p_gatesx, g_gatesx);
    cudaGetSymbolAddress(&p_lstm,   g_lstm);
    cudaGetSymbolAddress(&p_pimlog, g_pimlog);

    conv_kernel<<<BT, 128>>>(x, W1, b1, W2, b2, W3, b3, W4, b4);

    // gates_x = feat @ lstm_k + lstm_b  (4096 x 1024)
    sgemm_bias_kernel<<<dim3(1024 / 128, BT / 128), 256>>>(
        (const float*)p_feat, lstm_k, lstm_b, (float*)p_gatesx, BT, 1024, 256);

    lstm_kernel<<<BB / 2, 256>>>(lstm_r);

    // pim logits = lstm @ pim_W + pim_b (4096 x 4096)
    sgemm_bias_kernel<<<dim3(4096 / 128, BT / 128), 256>>>(
        (const float*)p_lstm, pim_W, pim_b, (float*)p_pimlog, BT, 4096, 256);

    pir_kernel<<<BT, 64>>>(pir_W, pir_b);
    pim_softmax_kernel<<<BT, 256>>>(mask, a_taken);
    vpred_kernel<<<BT, 32>>>(v_W, v_b);
    gae_stats_kernel<<<1, 1024>>>(GAE);
    pg_terms_kernel<<<16, 256>>>(lg_old, a_taken, GAE);
    vf_kernel<<<BT, 256>>>(old_v, rets);
    finalize_kernel<<<1, 1024>>>(out);
}

// round 3
// speedup vs baseline: 2.2361x; 2.2361x over previous
#include <cuda_runtime.h>
#include <math.h>

#define BT    4096
#define HID   256
#define TSTEP 64
#define BB    64

// ---------------- scratch (static device memory; no allocations) ----------------
__device__ float g_feat  [BT * HID];          // conv features (B*T, 256)
__device__ float g_gatesx[BT * 1024];         // x @ Wk + b
__device__ float g_lstm  [BT * HID];          // lstm hidden states
__device__ float g_Wr4   [256 * 1024];        // Wr packed: [k][j][gate] interleaved
__device__ float g_pimlog[16777216];          // pim logits (4096 x 4096)
__device__ float g_pir   [BT * 36];           // pir probabilities
__device__ float g_entpir[BT];
__device__ float g_entpim[BT];
__device__ float g_ppim  [BT];                // pim prob of taken action
__device__ float g_vpred [BT];
__device__ float g_pgvals[BT];
__device__ float g_vfvals[BT];
__device__ float g_stats [2];                 // gae mean, std

__device__ __forceinline__ float leaky(float v) { return v > 0.f ? v : 0.2f * v; }
__device__ __forceinline__ float sigmoidf(float v) { return 1.f / (1.f + expf(-v)); }

// ---------------- fused conv stack: one block per image ----------------
__global__ __launch_bounds__(128) void conv_kernel(
    const float* __restrict__ x,
    const float* __restrict__ W1, const float* __restrict__ b1,
    const float* __restrict__ W2, const float* __restrict__ b2,
    const float* __restrict__ W3, const float* __restrict__ b3,
    const float* __restrict__ W4, const float* __restrict__ b4)
{
    __shared__ float sx[832];   // 13*8*8
    __shared__ float h1[384];   // 6*4*16
    __shared__ float h2[480];   // 5*3*32
    __shared__ float h3[128];   // 2*1*64
    const int img = blockIdx.x;
    const float* xin = x + img * 832;
    for (int i = threadIdx.x; i < 832; i += blockDim.x) sx[i] = xin[i];
    __syncthreads();

    // conv1: (13,8,8) -> (6,4,16), k=2 s=2
    for (int idx = threadIdx.x; idx < 384; idx += blockDim.x) {
        int oc = idx & 15, sp = idx >> 4;
        int ow = sp & 3, oh = sp >> 2;
        float v = b1[oc];
        #pragma unroll
        for (int kh = 0; kh < 2; kh++)
        #pragma unroll
        for (int kw = 0; kw < 2; kw++) {
            const float* xp = &sx[((oh * 2 + kh) * 8 + (ow * 2 + kw)) * 8];
            const float* wp = &W1[((kh * 2 + kw) * 8) * 16 + oc];
            #pragma unroll
            for (int ic = 0; ic < 8; ic++) v += xp[ic] * wp[ic * 16];
        }
        h1[idx] = leaky(v);
    }
    __syncthreads();

    // conv2: (6,4,16) -> (5,3,32), k=2 s=1
    for (int idx = threadIdx.x; idx < 480; idx += blockDim.x) {
        int oc = idx & 31, sp = idx >> 5;
        int ow = sp % 3, oh = sp / 3;
        float v = b2[oc];
        #pragma unroll
        for (int kh = 0; kh < 2; kh++)
        #pragma unroll
        for (int kw = 0; kw < 2; kw++) {
            const float* hp = &h1[((oh + kh) * 4 + (ow + kw)) * 16];
            const float* wp = &W2[((kh * 2 + kw) * 16) * 32 + oc];
            #pragma unroll
            for (int ic = 0; ic < 16; ic++) v += hp[ic] * wp[ic * 32];
        }
        h2[idx] = leaky(v);
    }
    __syncthreads();

    // conv3: (5,3,32) -> (2,1,64), k=2 s=2
    for (int idx = threadIdx.x; idx < 128; idx += blockDim.x) {
        int oc = idx & 63, oh = idx >> 6;
        float v = b3[oc];
        #pragma unroll
        for (int kh = 0; kh < 2; kh++)
        #pragma unroll
        for (int kw = 0; kw < 2; kw++) {
            const float* hp = &h2[((oh * 2 + kh) * 3 + kw) * 32];
            const float* wp = &W3[((kh * 2 + kw) * 32) * 64 + oc];
            #pragma unroll
            for (int ic = 0; ic < 32; ic++) v += hp[ic] * wp[ic * 64];
        }
        h3[idx] = leaky(v);
    }
    __syncthreads();

    // conv4 1x1: (2,1,64)->(2,1,128) + channels_first flatten: feat[2*oc+oh]
    for (int idx = threadIdx.x; idx < 256; idx += blockDim.x) {
        int oc = idx >> 1, oh = idx & 1;
        float v = b4[oc];
        #pragma unroll
        for (int ic = 0; ic < 64; ic++) v += h3[oh * 64 + ic] * W4[ic * 128 + oc];
        g_feat[img * 256 + idx] = leaky(v);
    }
}

// ---------------- tiled SGEMM with bias (float4 tile loads) ----------------
__global__ __launch_bounds__(256) void sgemm_bias_kernel(
    const float* __restrict__ A, const float* __restrict__ B,
    const float* __restrict__ bias, float* __restrict__ C,
    int M, int N, int K)
{
    const int BM = 128, BN = 128, BK = 8, TM = 8, TN = 8;
    __shared__ float As[BK][BM];
    __shared__ float Bs[BK][BN];
    const int bcol = blockIdx.x, brow = blockIdx.y;
    const int tid = threadIdx.x;
    const int tx = tid % (BN / TN);     // 0..15
    const int ty = tid / (BN / TN);     // 0..15
    float acc[TM][TN];
    #pragma unroll
    for (int m = 0; m < TM; m++)
        #pragma unroll
        for (int n = 0; n < TN; n++) acc[m][n] = 0.f;
    float ar[TM], br[TN];
    const float* Ab = A + (size_t)brow * BM * K;
    const float* Bb = B + (size_t)bcol * BN;

    // vectorized tile-load indices
    const int a_r = tid >> 1;           // 0..127
    const int a_c = (tid & 1) << 2;     // 0 or 4
    const int b_r = tid >> 5;           // 0..7
    const int b_c = (tid & 31) << 2;    // 0..124

    for (int k0 = 0; k0 < K; k0 += BK) {
        float4 a4 = *(const float4*)&Ab[(size_t)a_r * K + k0 + a_c];
        As[a_c + 0][a_r] = a4.x; As[a_c + 1][a_r] = a4.y;
        As[a_c + 2][a_r] = a4.z; As[a_c + 3][a_r] = a4.w;
        float4 b4 = *(const float4*)&Bb[(size_t)(k0 + b_r) * N + b_c];
        *(float4*)&Bs[b_r][b_c] = b4;
        __syncthreads();
        #pragma unroll
        for (int kk = 0; kk < BK; kk++) {
            #pragma unroll
            for (int m = 0; m < TM; m++) ar[m] = As[kk][ty * TM + m];
            #pragma unroll
            for (int n = 0; n < TN; n++) br[n] = Bs[kk][tx * TN + n];
            #pragma unroll
            for (int m = 0; m < TM; m++)
                #pragma unroll
                for (int n = 0; n < TN; n++) acc[m][n] += ar[m] * br[n];
        }
        __syncthreads();
    }
    #pragma unroll
    for (int m = 0; m < TM; m++) {
        size_t row = (size_t)brow * BM + ty * TM + m;
        #pragma unroll
        for (int n = 0; n < TN; n++) {
            int col = bcol * BN + tx * TN + n;
            C[row * N + col] = acc[m][n] + bias[col];
        }
    }
}

// ---------------- pack Wr: Wr[k*1024 + g*256 + j] -> g_Wr4[k*1024 + j*4 + g] ----------------
__global__ __launch_bounds__(256) void pack_wr_kernel(const float* __restrict__ Wr)
{
    int idx = blockIdx.x * 256 + threadIdx.x;      // 262144 total
    int k = idx >> 10, col = idx & 1023;
    int g = col >> 8, j = col & 255;
    g_Wr4[(k << 10) + (j << 2) + g] = Wr[idx];
}

// ---------------- LSTM: 2 rows/block, 1024 threads, 4-way k split ----------------
__global__ __launch_bounds__(1024) void lstm_kernel()
{
    __shared__ float h[2][256];
    __shared__ float spE[8][4][256];   // [acc-slot][k-quarter][j] : conflict-free
    const int tid = threadIdx.x;
    const int j = tid & 255;
    const int q = tid >> 8;            // 0..3
    const int b0 = blockIdx.x * 2;
    const float4* __restrict__ Wr4 = (const float4*)g_Wr4;

    if (tid < 256) { h[0][tid] = 0.f; h[1][tid] = 0.f; }
    float c0 = 0.f, c1 = 0.f;
    __syncthreads();

    for (int t = 0; t < TSTEP; t++) {
        float a00 = 0.f, a10 = 0.f, a20 = 0.f, a30 = 0.f;
        float a01 = 0.f, a11 = 0.f, a21 = 0.f, a31 = 0.f;
        const int kbase = q << 6;      // q*64
        #pragma unroll 8
        for (int kk = 0; kk < 64; kk++) {
            int k = kbase + kk;
            float4 w = Wr4[(k << 8) + j];
            float h0 = h[0][k], h1 = h[1][k];
            a00 += w.x * h0; a10 += w.y * h0; a20 += w.z * h0; a30 += w.w * h0;
            a01 += w.x * h1; a11 += w.y * h1; a21 += w.z * h1; a31 += w.w * h1;
        }
        spE[0][q][j] = a00; spE[1][q][j] = a10; spE[2][q][j] = a20; spE[3][q][j] = a30;
        spE[4][q][j] = a01; spE[5][q][j] = a11; spE[6][q][j] = a21; spE[7][q][j] = a31;
        __syncthreads();

        if (tid < 256) {
            float z[8];
            #pragma unroll
            for (int e = 0; e < 8; e++)
                z[e] = spE[e][0][j] + spE[e][1][j] + spE[e][2][j] + spE[e][3][j];
            const size_t row0 = ((size_t)b0 * TSTEP + t) * 1024;
            const size_t row1 = row0 + (size_t)TSTEP * 1024;
            float zi0 = z[0] + g_gatesx[row0 + j];
            float zf0 = z[1] + g_gatesx[row0 + 256 + j];
            float zg0 = z[2] + g_gatesx[row0 + 512 + j];
            float zo0 = z[3] + g_gatesx[row0 + 768 + j];
            float zi1 = z[4] + g_gatesx[row1 + j];
            float zf1 = z[5] + g_gatesx[row1 + 256 + j];
            float zg1 = z[6] + g_gatesx[row1 + 512 + j];
            float zo1 = z[7] + g_gatesx[row1 + 768 + j];
            c0 = sigmoidf(zf0) * c0 + sigmoidf(zi0) * tanhf(zg0);
            float hn0 = sigmoidf(zo0) * tanhf(c0);
            c1 = sigmoidf(zf1) * c1 + sigmoidf(zi1) * tanhf(zg1);
            float hn1 = sigmoidf(zo1) * tanhf(c1);
            h[0][j] = hn0; h[1][j] = hn1;
            g_lstm[((size_t)b0 * TSTEP + t) * 256 + j] = hn0;
            g_lstm[((size_t)(b0 + 1) * TSTEP + t) * 256 + j] = hn1;
        }
        __syncthreads();
    }
}

// ---------------- pir head: logits + softmax + entropy (one block per row) ----------------
__global__ __launch_bounds__(64) void pir_kernel(const float* __restrict__ pir_W,
                                                 const float* __restrict__ pir_b)
{
    __shared__ float sh[256];
    __shared__ float lg[36];
    const int row = blockIdx.x;
    const int tid = threadIdx.x;
    for (int i = tid; i < 256; i += blockDim.x) sh[i] = g_lstm[(size_t)row * 256 + i];
    __syncthreads();
    if (tid < 36) {
        float v = pir_b[tid];
        for (int k = 0; k < 256; k++) v += sh[k] * pir_W[k * 36 + tid];
        lg[tid] = v;
    }
    __syncthreads();
    if (tid == 0) {
        float mx = -1e30f;
        for (int c = 0; c < 36; c++) mx = fmaxf(mx, lg[c]);
        float s = 0.f;
        for (int c = 0; c < 36; c++) s += expf(lg[c] - mx);
        float ent = 0.f;
        for (int c = 0; c < 36; c++) {
            float p = expf(lg[c] - mx) / s;
            g_pir[row * 36 + c] = p;
            ent += p * logf(p);
        }
        g_entpir[row] = ent;   // sum p log p (negative)
    }
}

// ---------------- pim softmax + mask + renorm + entropy + gather ----------------
__global__ __launch_bounds__(256) void pim_softmax_kernel(const int* __restrict__ mask,
                                                          const int* __restrict__ a_taken)
{
    __shared__ float red[256];
    __shared__ float s_mx, s_S, s_SM;
    const int row = blockIdx.x;
    const int tid = threadIdx.x;
    const float* lg = g_pimlog + (size_t)row * 4096;
    const int* mrow = mask + (size_t)row * 4096;

    // max
    float mx = -1e30f;
    for (int j = tid; j < 4096; j += 256) mx = fmaxf(mx, lg[j]);
    red[tid] = mx; __syncthreads();
    for (int s = 128; s > 0; s >>= 1) { if (tid < s) red[tid] = fmaxf(red[tid], red[tid + s]); __syncthreads(); }
    if (tid == 0) s_mx = red[0];
    __syncthreads();
    mx = s_mx;

    // total sum-exp and masked sum-exp
    float ssum = 0.f, smsum = 0.f;
    for (int j = tid; j < 4096; j += 256) {
        float q = expf(lg[j] - mx);
        ssum += q;
        if (mrow[j]) smsum += q;
    }
    __syncthreads();
    red[tid] = ssum; __syncthreads();
    for (int s = 128; s > 0; s >>= 1) { if (tid < s) red[tid] += red[tid + s]; __syncthreads(); }
    if (tid == 0) s_S = red[0];
    __syncthreads();
    red[tid] = smsum; __syncthreads();
    for (int s = 128; s > 0; s >>= 1) { if (tid < s) red[tid] += red[tid + s]; __syncthreads(); }
    if (tid == 0) s_SM = red[0];
    __syncthreads();

    const float denom = (s_SM > 0.f) ? s_SM : s_S;

    // entropy over masked entries (mask==0 entries contribute exactly 0)
    float ent = 0.f;
    for (int j = tid; j < 4096; j += 256) {
        if (mrow[j]) {
            float p = expf(lg[j] - mx) / denom;
            if (p > 0.f) ent += p * logf(p);
        }
    }
    __syncthreads();
    red[tid] = ent; __syncthreads();
    for (int s = 128; s > 0; s >>= 1) { if (tid < s) red[tid] += red[tid + s]; __syncthreads(); }
    if (tid == 0) {
        g_entpim[row] = red[0];
        int a = a_taken[row];
        float q = expf(lg[a] - mx);
        g_ppim[row] = mrow[a] ? q / denom : 0.f;
    }
}

// ---------------- value head ----------------
__global__ __launch_bounds__(32) void vpred_kernel(const float* __restrict__ v_W,
                                                   const float* __restrict__ v_b)
{
    const int row = blockIdx.x;
    const int lane = threadIdx.x;
    float s = 0.f;
    for (int k = lane; k < 256; k += 32) s += g_lstm[(size_t)row * 256 + k] * v_W[k];
    for (int o = 16; o > 0; o >>= 1) s += __shfl_down_sync(0xffffffffu, s, o);
    if (lane == 0) g_vpred[row] = s + v_b[0];
}

// ---------------- block-wide double sum (blockDim must be 1024) ----------------
__device__ double block_sum_d(double v)
{
    __shared__ double rd[1024];
    const int tid = threadIdx.x;
    __syncthreads();
    rd[tid] = v; __syncthreads();
    for (int s = 512; s > 0; s >>= 1) { if (tid < s) rd[tid] += rd[tid + s]; __syncthreads(); }
    double r = rd[0];
    __syncthreads();
    return r;
}

__global__ __launch_bounds__(1024) void gae_stats_kernel(const float* __restrict__ GAE)
{
    const int tid = threadIdx.x;
    double s = 0.0;
    for (int i = tid; i < BT; i += 1024) s += (double)GAE[i];
    double tot = block_sum_d(s);
    double mean = tot / (double)BT;
    double v = 0.0;
    for (int i = tid; i < BT; i += 1024) { double d = (double)GAE[i] - mean; v += d * d; }
    double var = block_sum_d(v) / (double)BT;
    if (tid == 0) { g_stats[0] = (float)mean; g_stats[1] = (float)sqrt(var); }
}

__global__ void pg_terms_kernel(const float* __restrict__ lg_old,
                                const int* __restrict__ a_taken,
                                const float* __restrict__ GAE)
{
    const int i = blockIdx.x * blockDim.x + threadIdx.x;
    if (i >= BT) return;
    const float mean = g_stats[0], std = g_stats[1];
    float g = (GAE[i] - mean) / (std + 1e-8f);
    int a = a_taken[i];
    float p = ((i & 1) == 0) ? g_pir[i * 36 + a] : g_ppim[i];
    float lgn = logf(p);
    float rt = expf(lgn - lg_old[i]);
    float rtc = fminf(fmaxf(rt, 0.8f), 1.2f);
    g_pgvals[i] = fmaxf(-g * rt, -g * rtc);
}

// vf broadcast loss: block i sums over j
__global__ __launch_bounds__(256) void vf_kernel(const float* __restrict__ old_v,
                                                 const float* __restrict__ ret)
{
    __shared__ float red[256];
    const int i = blockIdx.x;
    const int tid = threadIdx.x;
    const float vp = g_vpred[i];
    float s = 0.f;
    for (int j = tid; j < BT; j += 256) {
        float r = ret[j];
        float ov = old_v[j];
        float d1 = vp - r;
        float dc = fminf(fmaxf(vp - ov, -0.2f), 0.2f);
        float d2 = ov + dc - r;
        s += fmaxf(d1 * d1, d2 * d2);
    }
    red[tid] = s; __syncthreads();
    for (int st = 128; st > 0; st >>= 1) { if (tid < st) red[tid] += red[tid + st]; __syncthreads(); }
    if (tid == 0) g_vfvals[i] = red[0];
}

__global__ __launch_bounds__(1024) void finalize_kernel(float* __restrict__ out)
{
    const int tid = threadIdx.x;
    double s = 0.0;
    for (int i = tid; i < BT; i += 1024) s += (double)g_pgvals[i];
    double pg = block_sum_d(s) / (double)BT;

    s = 0.0;
    for (int i = tid; i < BT; i += 1024) s += (double)g_entpir[i] + (double)g_entpim[i];
    double entropy = -block_sum_d(s);

    s = 0.0;
    for (int i = tid; i < BT; i += 1024) s += (double)g_vfvals[i];
    double vf = 0.5 * block_sum_d(s) / ((double)BT * (double)BT);

    if (tid == 0) {
        out[0] = (float)(pg - entropy + vf);
        out[1] = (float)pg;
        out[2] = (float)entropy;
        out[3] = (float)vf;
    }
}

// ---------------- launcher ----------------
extern "C" void kernel_launch(void* const* d_in, const int* in_sizes, int n_in,
                              void* d_out, int out_size)
{
    const float* x       = (const float*)d_in[0];
    const int*   mask    = (const int*)  d_in[1];
    const float* lg_old  = (const float*)d_in[2];
    const int*   a_taken = (const int*)  d_in[3];
    const float* GAE     = (const float*)d_in[4];
    const float* old_v   = (const float*)d_in[5];
    const float* rets    = (const float*)d_in[6];
    const float* W1 = (const float*)d_in[7];  const float* b1 = (const float*)d_in[8];
    const float* W2 = (const float*)d_in[9];  const float* b2 = (const float*)d_in[10];
    const float* W3 = (const float*)d_in[11]; const float* b3 = (const float*)d_in[12];
    const float* W4 = (const float*)d_in[13]; const float* b4 = (const float*)d_in[14];
    const float* lstm_k = (const float*)d_in[15];
    const float* lstm_r = (const float*)d_in[16];
    const float* lstm_b = (const float*)d_in[17];
    const float* pir_W  = (const float*)d_in[18];
    const float* pir_b  = (const float*)d_in[19];
    const float* pim_W  = (const float*)d_in[20];
    const float* pim_b  = (const float*)d_in[21];
    const float* v_W    = (const float*)d_in[22];
    const float* v_b    = (const float*)d_in[23];
    float* out = (float*)d_out;

    void *p_feat, *p_gatesx, *p_lstm, *p_pimlog;
    cudaGetSymbolAddress(&p_feat,   g_feat);
    cudaGetSymbolAddress(&p_gatesx, g_gatesx);
    cudaGetSymbolAddress(&p_lstm,   g_lstm);
    cudaGetSymbolAddress(&p_pimlog, g_pimlog);

    conv_kernel<<<BT, 128>>>(x, W1, b1, W2, b2, W3, b3, W4, b4);
    pack_wr_kernel<<<1024, 256>>>(lstm_r);

    // gates_x = feat @ lstm_k + lstm_b  (4096 x 1024)
    sgemm_bias_kernel<<<dim3(1024 / 128, BT / 128), 256>>>(
        (const float*)p_feat, lstm_k, lstm_b, (float*)p_gatesx, BT, 1024, 256);

    lstm_kernel<<<BB / 2, 1024>>>();

    // pim logits = lstm @ pim_W + pim_b (4096 x 4096)
    sgemm_bias_kernel<<<dim3(4096 / 128, BT / 128), 256>>>(
        (const float*)p_lstm, pim_W, pim_b, (float*)p_pimlog, BT, 4096, 256);

    pir_kernel<<<BT, 64>>>(pir_W, pir_b);
    pim_softmax_kernel<<<BT, 256>>>(mask, a_taken);
    vpred_kernel<<<BT, 32>>>(v_W, v_b);
    gae_stats_kernel<<<1, 1024>>>(GAE);
    pg_terms_kernel<<<16, 256>>>(lg_old, a_taken, GAE);
    vf_kernel<<<BT, 256>>>(old_v, rets);
    finalize_kernel<<<1, 1024>>>(out);
}